// round 4
// baseline (speedup 1.0000x reference)
#include <cuda_runtime.h>
#include <cuda_bf16.h>
#include <cstdint>

// ============================================================================
// ModularLinear on GB300 — base-arch build (no tcgen05/TMA: ptxas targets
// sm_103 non-'a'). Strategy: mma.sync HMMA.16816 bf16 with fp32 accumulate,
// 3-term hi/lo split for fp32-class precision, cp.async double buffering.
//
//   out[t, b, kk*1024 + o] = sum_i x[t, b, i] * w[sel[b,kk], o, i]
//   16 independent GEMMs of 2048 x 1024 x 1024 (fp32).
// ============================================================================

#define T_DIM   2048
#define B_DIM   8
#define IN_DIM  1024
#define OUT_DIM 1024
#define K_SEL   2

#define TILE_M  128
#define TILE_N  128
#define KC      32                        // K-chunk (fp32 elements)
#define NCHUNK  (IN_DIM / KC)             // 32
#define THREADS 256

// SMEM: fp32 tiles, rows padded 128B -> 144B (LDS.64 frag loads hit the
// 2-phase minimum; 144 is a multiple of 16 so cp.async dst stays aligned).
#define ROW_BYTES   144
#define A_BYTES     (TILE_M * ROW_BYTES)          // 18432
#define B_BYTES     (TILE_N * ROW_BYTES)          // 18432
#define STAGE_BYTES (A_BYTES + B_BYTES)           // 36864
#define SMEM_TOTAL  (2 * STAGE_BYTES)             // 73728

// ---------------------------------------------------------------------------
// PTX helpers (base-arch only: cp.async + mma.sync)
// ---------------------------------------------------------------------------
__device__ __forceinline__ void cp16(uint32_t dst_smem, const void* src) {
    asm volatile("cp.async.cg.shared.global [%0], [%1], 16;"
                 :: "r"(dst_smem), "l"(src) : "memory");
}
#define CP_COMMIT() asm volatile("cp.async.commit_group;" ::: "memory")
#define CP_WAIT(n)  asm volatile("cp.async.wait_group %0;" :: "n"(n) : "memory")

__device__ __forceinline__ uint32_t smem_u32(const void* p) {
    uint32_t a;
    asm("{ .reg .u64 t; cvta.to.shared.u64 t, %1; cvt.u32.u64 %0, t; }"
        : "=r"(a) : "l"(p));
    return a;
}

// D += A * B  (m16n8k16, bf16 in, fp32 acc)
__device__ __forceinline__ void mma16816(float* c, const uint32_t* a,
                                         const uint32_t* b) {
    asm volatile(
        "mma.sync.aligned.m16n8k16.row.col.f32.bf16.bf16.f32 "
        "{%0,%1,%2,%3}, {%4,%5,%6,%7}, {%8,%9}, {%0,%1,%2,%3};"
        : "+f"(c[0]), "+f"(c[1]), "+f"(c[2]), "+f"(c[3])
        : "r"(a[0]), "r"(a[1]), "r"(a[2]), "r"(a[3]),
          "r"(b[0]), "r"(b[1]));
}

// Split a pair of fp32 into packed bf16x2 hi (truncation = top 16 bits, one
// PRMT) and bf16x2 lo (residual, exact to ~2^-17). Low half of each .b32 =
// even-k element, matching the mma fragment layout.
__device__ __forceinline__ void split_pair(uint2 v, uint32_t& hi, uint32_t& lo) {
    hi = __byte_perm(v.x, v.y, 0x7632);
    float f0 = __uint_as_float(v.x);
    float f1 = __uint_as_float(v.y);
    float l0 = f0 - __uint_as_float(v.x & 0xFFFF0000u);
    float l1 = f1 - __uint_as_float(v.y & 0xFFFF0000u);
    __nv_bfloat162 p = __float22bfloat162_rn(make_float2(l0, l1));
    lo = *reinterpret_cast<uint32_t*>(&p);
}

// ============================================================================
// Kernel
// ============================================================================
__global__ void __launch_bounds__(THREADS, 1)
modlin_kernel(const float* __restrict__ x, const int* __restrict__ sel,
              const float* __restrict__ w, float* __restrict__ out)
{
    extern __shared__ char smem[];
    const int tid = threadIdx.x;
    const int wid = tid >> 5;
    const int lid = tid & 31;

    const int nt_blk = blockIdx.x;            // 0..7
    const int mt_blk = blockIdx.y;            // 0..15
    const int pi     = blockIdx.z;            // 0..15  (b,k) pair
    const int b  = pi >> 1;
    const int kk = pi & 1;
    const int m0 = mt_blk * TILE_M;
    const int n0 = nt_blk * TILE_N;

    const int e = sel[b * K_SEL + kk];

    // x[t, b, i]: row t stride = B_DIM*IN_DIM floats
    const float* Abase = x + (((size_t)m0 * B_DIM + b) << 10);
    // w[e, o, i]: row o stride = IN_DIM floats
    const float* Bbase = w + ((((size_t)e << 10) + (size_t)n0) << 10);

    const uint32_t smem_base = smem_u32(smem);

    // ---- cp.async producer: one K-chunk (A 128x32 f32 + B 128x32 f32) ----
    auto issue_chunk = [&](int c, int s) {
        const int kbase = c * KC;
        const uint32_t aSt = smem_base + s * STAGE_BYTES;
        const uint32_t bSt = aSt + A_BYTES;
        #pragma unroll
        for (int it = 0; it < (TILE_M * 8) / THREADS; ++it) {   // 4
            int idx = tid + it * THREADS;
            int row = idx >> 3, q = idx & 7;
            cp16(aSt + row * ROW_BYTES + q * 16,
                 Abase + (size_t)row * (B_DIM * IN_DIM) + kbase + q * 4);
        }
        #pragma unroll
        for (int it = 0; it < (TILE_N * 8) / THREADS; ++it) {   // 4
            int idx = tid + it * THREADS;
            int row = idx >> 3, q = idx & 7;
            cp16(bSt + row * ROW_BYTES + q * 16,
                 Bbase + (size_t)row * IN_DIM + kbase + q * 4);
        }
    };

    // warp layout: 4 (m) x 2 (n); warp tile 32 x 64
    const int warp_m = (wid & 3) * 32;
    const int warp_n = (wid >> 2) * 64;
    const int qr = lid >> 2;     // fragment row 0..7
    const int qc = lid & 3;      // fragment k-pair / n-pair col

    float acc[2][8][4];
    #pragma unroll
    for (int i = 0; i < 2; ++i)
        #pragma unroll
        for (int j = 0; j < 8; ++j)
            #pragma unroll
            for (int v = 0; v < 4; ++v) acc[i][j][v] = 0.0f;

    issue_chunk(0, 0);
    CP_COMMIT();

    for (int c = 0; c < NCHUNK; ++c) {
        const int s = c & 1;
        if (c + 1 < NCHUNK) {
            issue_chunk(c + 1, s ^ 1);
            CP_COMMIT();
            CP_WAIT(1);
        } else {
            CP_WAIT(0);
        }
        __syncthreads();

        // ---- compute on stage s ----
        const char* st = smem + s * STAGE_BYTES;
        const char* aS = st;
        const char* bS = st + A_BYTES;
        const char* aBase0 = aS + (warp_m + qr) * ROW_BYTES + qc * 8;
        const char* bBase0 = bS + (warp_n + qr) * ROW_BYTES + qc * 8;

        #pragma unroll
        for (int k16 = 0; k16 < 2; ++k16) {
            // A fragments: 2 m-tiles, load f32 once, derive hi+lo
            uint32_t ah[2][4], al[2][4];
            #pragma unroll
            for (int mt = 0; mt < 2; ++mt) {
                const char* p = aBase0 + mt * 16 * ROW_BYTES + k16 * 64;
                uint2 x0 = *reinterpret_cast<const uint2*>(p);
                uint2 x1 = *reinterpret_cast<const uint2*>(p + 8 * ROW_BYTES);
                uint2 x2 = *reinterpret_cast<const uint2*>(p + 32);
                uint2 x3 = *reinterpret_cast<const uint2*>(p + 8 * ROW_BYTES + 32);
                split_pair(x0, ah[mt][0], al[mt][0]);
                split_pair(x1, ah[mt][1], al[mt][1]);
                split_pair(x2, ah[mt][2], al[mt][2]);
                split_pair(x3, ah[mt][3], al[mt][3]);
            }
            // B fragments: 8 n-tiles
            uint32_t bh[8][2], bl[8][2];
            #pragma unroll
            for (int nt = 0; nt < 8; ++nt) {
                const char* p = bBase0 + nt * 8 * ROW_BYTES + k16 * 64;
                uint2 x0 = *reinterpret_cast<const uint2*>(p);
                uint2 x1 = *reinterpret_cast<const uint2*>(p + 32);
                split_pair(x0, bh[nt][0], bl[nt][0]);
                split_pair(x1, bh[nt][1], bl[nt][1]);
            }
            // 3-term split MMAs: hh + hl + lh
            #pragma unroll
            for (int mt = 0; mt < 2; ++mt)
                #pragma unroll
                for (int nt = 0; nt < 8; ++nt) {
                    mma16816(acc[mt][nt], ah[mt], bh[nt]);
                    mma16816(acc[mt][nt], ah[mt], bl[nt]);
                    mma16816(acc[mt][nt], al[mt], bh[nt]);
                }
        }
        __syncthreads();
    }

    // ---- epilogue: direct fp32 stores ----
    const size_t row_stride = (size_t)B_DIM * K_SEL * OUT_DIM;   // 16384 floats
    #pragma unroll
    for (int mt = 0; mt < 2; ++mt) {
        const int t = m0 + warp_m + mt * 16 + qr;
        float* orow = out + (size_t)t * row_stride
                          + ((size_t)b * K_SEL + kk) * OUT_DIM
                          + n0 + warp_n + qc * 2;
        #pragma unroll
        for (int nt = 0; nt < 8; ++nt) {
            float2 v0 = make_float2(acc[mt][nt][0], acc[mt][nt][1]);
            float2 v1 = make_float2(acc[mt][nt][2], acc[mt][nt][3]);
            *reinterpret_cast<float2*>(orow + nt * 8) = v0;
            *reinterpret_cast<float2*>(orow + nt * 8 + 8 * row_stride) = v1;
        }
    }
}

// ============================================================================
// Launch
// ============================================================================
extern "C" void kernel_launch(void* const* d_in, const int* in_sizes, int n_in,
                              void* d_out, int out_size) {
    (void)in_sizes; (void)n_in; (void)out_size;
    const float* x   = (const float*)d_in[0];
    const int*   sel = (const int*)d_in[1];
    const float* w   = (const float*)d_in[2];
    float*       out = (float*)d_out;

    cudaFuncSetAttribute(modlin_kernel,
                         cudaFuncAttributeMaxDynamicSharedMemorySize, SMEM_TOTAL);

    dim3 grid(OUT_DIM / TILE_N,            // 8
              T_DIM / TILE_M,              // 16
              B_DIM * K_SEL);              // 16
    modlin_kernel<<<grid, THREADS, SMEM_TOTAL>>>(x, sel, w, out);
}

// round 5
// speedup vs baseline: 1.1797x; 1.1797x over previous
#include <cuda_runtime.h>
#include <cuda_bf16.h>
#include <cstdint>

// ============================================================================
// ModularLinear on GB300 — base-arch build (mma.sync HMMA.16816 bf16, fp32 acc,
// 3-term hi/lo split). R5: hi/lo split moved to a once-per-element convert pass
// (cp.async fp32 staging -> bf16 hi/lo tiles in SMEM), mainloop is ldmatrix +
// MMA only; convert of chunk c+1 overlaps tensor drain of chunk c.
//
//   out[t, b, kk*1024 + o] = sum_i x[t, b, i] * w[sel[b,kk], o, i]
//   16 independent GEMMs of 2048 x 1024 x 1024 (fp32).
// ============================================================================

#define T_DIM   2048
#define B_DIM   8
#define IN_DIM  1024
#define OUT_DIM 1024
#define K_SEL   2

#define TILE_M  128
#define TILE_N  128
#define KC      32                         // K-chunk (fp32 elements)
#define NCHUNK  (IN_DIM / KC)              // 32
#define THREADS 256

// ---- SMEM layout ----
// fp32 staging (cp.async targets), flat row-major [row][k] per tile:
#define STG_TILE    (TILE_M * KC * 4)      // 16384
#define STG_STAGE   (2 * STG_TILE)         // A + B = 32768
// bf16 tiles (convert output), row = 64B (KC bf16), SW64-swizzled:
#define BF_TILE     (TILE_M * KC * 2)      // 8192
#define BF_STAGE    (4 * BF_TILE)          // Ah, Al, Bh, Bl = 32768
#define OFF_BF      (2 * STG_STAGE)        // 65536
#define SMEM_TOTAL  (OFF_BF + 2 * BF_STAGE)   // 131072

// ---------------------------------------------------------------------------
// PTX helpers (base-arch only)
// ---------------------------------------------------------------------------
__device__ __forceinline__ void cp16(uint32_t dst_smem, const void* src) {
    asm volatile("cp.async.cg.shared.global [%0], [%1], 16;"
                 :: "r"(dst_smem), "l"(src) : "memory");
}
#define CP_COMMIT() asm volatile("cp.async.commit_group;" ::: "memory")
#define CP_WAIT(n)  asm volatile("cp.async.wait_group %0;" :: "n"(n) : "memory")

__device__ __forceinline__ uint32_t smem_u32(const void* p) {
    uint32_t a;
    asm("{ .reg .u64 t; cvta.to.shared.u64 t, %1; cvt.u32.u64 %0, t; }"
        : "=r"(a) : "l"(p));
    return a;
}

__device__ __forceinline__ void ldsm4(uint32_t* r, uint32_t addr) {
    asm volatile("ldmatrix.sync.aligned.m8n8.x4.shared.b16 {%0,%1,%2,%3}, [%4];"
                 : "=r"(r[0]), "=r"(r[1]), "=r"(r[2]), "=r"(r[3])
                 : "r"(addr));
}

// D += A * B  (m16n8k16, bf16 in, fp32 acc)
__device__ __forceinline__ void mma16816(float* c, const uint32_t* a,
                                         const uint32_t* b) {
    asm volatile(
        "mma.sync.aligned.m16n8k16.row.col.f32.bf16.bf16.f32 "
        "{%0,%1,%2,%3}, {%4,%5,%6,%7}, {%8,%9}, {%0,%1,%2,%3};"
        : "+f"(c[0]), "+f"(c[1]), "+f"(c[2]), "+f"(c[3])
        : "r"(a[0]), "r"(a[1]), "r"(a[2]), "r"(a[3]),
          "r"(b[0]), "r"(b[1]));
}

// SW64 swizzle for 64B rows (8 rows x 64B atom): bits[5:4] ^= bits[8:7]
__device__ __forceinline__ uint32_t sw64(uint32_t bo) {
    return bo ^ ((bo >> 3) & 0x30);
}

// split 4 consecutive fp32 (as uint4) into 2 packed bf16x2 hi + 2 lo words
__device__ __forceinline__ void split_quad(uint4 u, uint2& hi, uint2& lo) {
    hi.x = __byte_perm(u.x, u.y, 0x7632);          // truncated bf16 pair
    hi.y = __byte_perm(u.z, u.w, 0x7632);
    float l0 = __uint_as_float(u.x) - __uint_as_float(u.x & 0xFFFF0000u);
    float l1 = __uint_as_float(u.y) - __uint_as_float(u.y & 0xFFFF0000u);
    float l2 = __uint_as_float(u.z) - __uint_as_float(u.z & 0xFFFF0000u);
    float l3 = __uint_as_float(u.w) - __uint_as_float(u.w & 0xFFFF0000u);
    __nv_bfloat162 p0 = __float22bfloat162_rn(make_float2(l0, l1));
    __nv_bfloat162 p1 = __float22bfloat162_rn(make_float2(l2, l3));
    lo.x = *reinterpret_cast<uint32_t*>(&p0);
    lo.y = *reinterpret_cast<uint32_t*>(&p1);
}

// ============================================================================
// Kernel
// ============================================================================
__global__ void __launch_bounds__(THREADS, 1)
modlin_kernel(const float* __restrict__ x, const int* __restrict__ sel,
              const float* __restrict__ w, float* __restrict__ out)
{
    extern __shared__ char smem[];
    const int tid = threadIdx.x;
    const int wid = tid >> 5;
    const int lid = tid & 31;

    const int nt_blk = blockIdx.x;            // 0..7
    const int mt_blk = blockIdx.y;            // 0..15
    const int pi     = blockIdx.z;            // 0..15  (b,k) pair
    const int b  = pi >> 1;
    const int kk = pi & 1;
    const int m0 = mt_blk * TILE_M;
    const int n0 = nt_blk * TILE_N;

    const int e = sel[b * K_SEL + kk];

    const float* Abase = x + (((size_t)m0 * B_DIM + b) << 10);         // stride B*IN per row
    const float* Bbase = w + ((((size_t)e << 10) + (size_t)n0) << 10); // stride IN per row

    const uint32_t smem_base = smem_u32(smem);

    // ---- cp.async producer: flat fp32 staging [row][k] ----
    auto issue_chunk = [&](int c, int s) {
        const int kbase = c * KC;
        const uint32_t aSt = smem_base + s * STG_STAGE;
        const uint32_t bSt = aSt + STG_TILE;
        #pragma unroll
        for (int j = 0; j < 4; ++j) {
            int f = tid + j * THREADS;         // float4 index 0..1023
            int row = f >> 3, kq = f & 7;
            cp16(aSt + f * 16,
                 Abase + (size_t)row * (B_DIM * IN_DIM) + kbase + kq * 4);
        }
        #pragma unroll
        for (int j = 0; j < 4; ++j) {
            int f = tid + j * THREADS;
            int row = f >> 3, kq = f & 7;
            cp16(bSt + f * 16,
                 Bbase + (size_t)row * IN_DIM + kbase + kq * 4);
        }
    };

    // ---- convert pass: staged fp32 -> bf16 hi/lo tiles (SW64-swizzled) ----
    auto convert_chunk = [&](int sStg, int sBf) {
        const char* stg = smem + sStg * STG_STAGE;
        char* bf = smem + OFF_BF + sBf * BF_STAGE;
        #pragma unroll
        for (int half = 0; half < 2; ++half) {         // 0 = A, 1 = B
            const char* src = stg + half * STG_TILE;
            char* hiT = bf + half * 2 * BF_TILE;       // Ah or Bh
            char* loT = hiT + BF_TILE;                 // Al or Bl
            #pragma unroll
            for (int j = 0; j < 4; ++j) {
                int f = tid + j * THREADS;             // float4 index
                int row = f >> 3, kq = f & 7;
                uint4 v = *reinterpret_cast<const uint4*>(src + f * 16);
                uint2 hi, lo;
                split_quad(v, hi, lo);
                uint32_t sw = sw64((uint32_t)(row * 64 + kq * 8));
                *reinterpret_cast<uint2*>(hiT + sw) = hi;
                *reinterpret_cast<uint2*>(loT + sw) = lo;
            }
        }
    };

    // ---- per-warp fragment geometry ----
    const int warp_m = (wid & 3) * 32;     // 4 warps in m
    const int warp_n = (wid >> 2) * 64;    // 2 warps in n
    const int tile = lid >> 3;             // ldmatrix sub-tile 0..3
    const int trow = lid & 7;
    const int qr = lid >> 2;               // mma fragment row
    const int qc = lid & 3;

    // ldmatrix relative offsets (swizzle-invariant to 8KB-aligned tile bases)
    uint32_t aOff[2][2], bOff[4][2];
    #pragma unroll
    for (int mt = 0; mt < 2; ++mt)
        #pragma unroll
        for (int k16 = 0; k16 < 2; ++k16) {
            int row = warp_m + mt * 16 + ((tile & 1) << 3) + trow;
            int kb  = k16 * 32 + ((tile >> 1) << 4);
            aOff[mt][k16] = sw64((uint32_t)(row * 64 + kb));
        }
    #pragma unroll
    for (int nt2 = 0; nt2 < 4; ++nt2)
        #pragma unroll
        for (int k16 = 0; k16 < 2; ++k16) {
            int row = warp_n + nt2 * 16 + ((tile >> 1) << 3) + trow;
            int kb  = k16 * 32 + ((tile & 1) << 4);
            bOff[nt2][k16] = sw64((uint32_t)(row * 64 + kb));
        }

    float acc[2][8][4];
    #pragma unroll
    for (int i = 0; i < 2; ++i)
        #pragma unroll
        for (int j = 0; j < 8; ++j)
            #pragma unroll
            for (int v = 0; v < 4; ++v) acc[i][j][v] = 0.0f;

    // ---- prologue ----
    issue_chunk(0, 0); CP_COMMIT();
    issue_chunk(1, 1); CP_COMMIT();
    CP_WAIT(1);
    __syncthreads();
    convert_chunk(0, 0);
    __syncthreads();

    // ---- mainloop ----
    for (int c = 0; c < NCHUNK; ++c) {
        const int s = c & 1;

        if (c + 2 < NCHUNK) { issue_chunk(c + 2, s); CP_COMMIT(); }
        if (c + 1 < NCHUNK) {
            if (c + 2 < NCHUNK) CP_WAIT(1); else CP_WAIT(0);
            __syncthreads();
        }

        // -- compute chunk c from bf16[s]: issue all MMAs first --
        {
            const uint32_t bfB = smem_base + OFF_BF + s * BF_STAGE;
            const uint32_t ahB = bfB;
            const uint32_t alB = bfB + BF_TILE;
            const uint32_t bhB = bfB + 2 * BF_TILE;
            const uint32_t blB = bfB + 3 * BF_TILE;
            #pragma unroll
            for (int k16 = 0; k16 < 2; ++k16) {
                uint32_t ah[2][4], al[2][4], bh[8][2], bl[8][2];
                #pragma unroll
                for (int mt = 0; mt < 2; ++mt) {
                    ldsm4(ah[mt], ahB + aOff[mt][k16]);
                    ldsm4(al[mt], alB + aOff[mt][k16]);
                }
                #pragma unroll
                for (int nt2 = 0; nt2 < 4; ++nt2) {
                    uint32_t r[4];
                    ldsm4(r, bhB + bOff[nt2][k16]);
                    bh[2 * nt2][0] = r[0]; bh[2 * nt2][1] = r[1];
                    bh[2 * nt2 + 1][0] = r[2]; bh[2 * nt2 + 1][1] = r[3];
                    ldsm4(r, blB + bOff[nt2][k16]);
                    bl[2 * nt2][0] = r[0]; bl[2 * nt2][1] = r[1];
                    bl[2 * nt2 + 1][0] = r[2]; bl[2 * nt2 + 1][1] = r[3];
                }
                // hh, hl, lh — 16 independent accs between dependent reuses
                #pragma unroll
                for (int mt = 0; mt < 2; ++mt)
                    #pragma unroll
                    for (int nt = 0; nt < 8; ++nt)
                        mma16816(acc[mt][nt], ah[mt], bh[nt]);
                #pragma unroll
                for (int mt = 0; mt < 2; ++mt)
                    #pragma unroll
                    for (int nt = 0; nt < 8; ++nt)
                        mma16816(acc[mt][nt], ah[mt], bl[nt]);
                #pragma unroll
                for (int mt = 0; mt < 2; ++mt)
                    #pragma unroll
                    for (int nt = 0; nt < 8; ++nt)
                        mma16816(acc[mt][nt], al[mt], bh[nt]);
            }
        }

        // -- convert chunk c+1 while the tensor pipe drains chunk c --
        if (c + 1 < NCHUNK) convert_chunk(s ^ 1, s ^ 1);

        __syncthreads();
    }

    // ---- epilogue: direct fp32 stores ----
    const size_t row_stride = (size_t)B_DIM * K_SEL * OUT_DIM;   // 16384 floats
    #pragma unroll
    for (int mt = 0; mt < 2; ++mt) {
        const int t = m0 + warp_m + mt * 16 + qr;
        float* orow = out + (size_t)t * row_stride
                          + ((size_t)b * K_SEL + kk) * OUT_DIM
                          + n0 + warp_n + qc * 2;
        #pragma unroll
        for (int nt = 0; nt < 8; ++nt) {
            float2 v0 = make_float2(acc[mt][nt][0], acc[mt][nt][1]);
            float2 v1 = make_float2(acc[mt][nt][2], acc[mt][nt][3]);
            *reinterpret_cast<float2*>(orow + nt * 8) = v0;
            *reinterpret_cast<float2*>(orow + nt * 8 + 8 * row_stride) = v1;
        }
    }
}

// ============================================================================
// Launch
// ============================================================================
extern "C" void kernel_launch(void* const* d_in, const int* in_sizes, int n_in,
                              void* d_out, int out_size) {
    (void)in_sizes; (void)n_in; (void)out_size;
    const float* x   = (const float*)d_in[0];
    const int*   sel = (const int*)d_in[1];
    const float* w   = (const float*)d_in[2];
    float*       out = (float*)d_out;

    cudaFuncSetAttribute(modlin_kernel,
                         cudaFuncAttributeMaxDynamicSharedMemorySize, SMEM_TOTAL);

    dim3 grid(OUT_DIM / TILE_N,            // 8
              T_DIM / TILE_M,              // 16
              B_DIM * K_SEL);              // 16
    modlin_kernel<<<grid, THREADS, SMEM_TOTAL>>>(x, sel, w, out);
}

// round 7
// speedup vs baseline: 1.5236x; 1.2915x over previous
#include <cuda_runtime.h>
#include <cuda_bf16.h>
#include <cstdint>

// ============================================================================
// ModularLinear on GB300 — base-arch build (mma.sync HMMA.16816 bf16, fp32
// acc, 3-term hi/lo split). R7 = R6 resubmit (R6 hit an infra failure, no
// data): warp-specialized producer/consumer with a 4-stage bf16 ring and
// named-barrier handshakes. Consumers run ldmatrix+MMA only; producers do
// LDG fp32 -> split -> swizzled STS bf16.
//
//   out[t, b, kk*1024 + o] = sum_i x[t, b, i] * w[sel[b,kk], o, i]
//   16 independent GEMMs of 2048 x 1024 x 1024 (fp32).
// ============================================================================

#define T_DIM   2048
#define B_DIM   8
#define IN_DIM  1024
#define OUT_DIM 1024
#define K_SEL   2

#define TILE_M  128
#define TILE_N  128
#define KC      32                         // K-chunk (fp32 elements)
#define NCHUNK  (IN_DIM / KC)              // 32
#define THREADS 384                        // 256 consumer + 128 producer
#define NSTG    4

// bf16 tile: 128 rows x 32 bf16 (64B rows), SW64-swizzled -> 8KB
#define BF_TILE     (TILE_M * KC * 2)      // 8192
#define STAGE_BYTES (4 * BF_TILE)          // Ah, Al, Bh, Bl = 32768
#define SMEM_TOTAL  (NSTG * STAGE_BYTES)   // 131072

// ---------------------------------------------------------------------------
// PTX helpers (base-arch only)
// ---------------------------------------------------------------------------
__device__ __forceinline__ uint32_t smem_u32(const void* p) {
    uint32_t a;
    asm("{ .reg .u64 t; cvta.to.shared.u64 t, %1; cvt.u32.u64 %0, t; }"
        : "=r"(a) : "l"(p));
    return a;
}

#define BAR_SYNC(id)   asm volatile("bar.sync %0, %1;"   :: "r"(id), "n"(THREADS) : "memory")
#define BAR_ARRIVE(id) asm volatile("bar.arrive %0, %1;" :: "r"(id), "n"(THREADS) : "memory")

__device__ __forceinline__ void ldsm4(uint32_t* r, uint32_t addr) {
    asm volatile("ldmatrix.sync.aligned.m8n8.x4.shared.b16 {%0,%1,%2,%3}, [%4];"
                 : "=r"(r[0]), "=r"(r[1]), "=r"(r[2]), "=r"(r[3])
                 : "r"(addr));
}

// D += A * B  (m16n8k16, bf16 in, fp32 acc)
__device__ __forceinline__ void mma16816(float* c, const uint32_t* a,
                                         const uint32_t* b) {
    asm volatile(
        "mma.sync.aligned.m16n8k16.row.col.f32.bf16.bf16.f32 "
        "{%0,%1,%2,%3}, {%4,%5,%6,%7}, {%8,%9}, {%0,%1,%2,%3};"
        : "+f"(c[0]), "+f"(c[1]), "+f"(c[2]), "+f"(c[3])
        : "r"(a[0]), "r"(a[1]), "r"(a[2]), "r"(a[3]),
          "r"(b[0]), "r"(b[1]));
}

// SW64 swizzle for 64B rows (8-row x 64B atom): bits[5:4] ^= bits[8:7]
__device__ __forceinline__ uint32_t sw64(uint32_t bo) {
    return bo ^ ((bo >> 3) & 0x30);
}

// split 8 consecutive fp32 (two uint4) into hi uint4 + lo uint4 (bf16x2 x4)
__device__ __forceinline__ void split_oct(uint4 u0, uint4 u1,
                                          uint4& hi, uint4& lo) {
    hi.x = __byte_perm(u0.x, u0.y, 0x7632);
    hi.y = __byte_perm(u0.z, u0.w, 0x7632);
    hi.z = __byte_perm(u1.x, u1.y, 0x7632);
    hi.w = __byte_perm(u1.z, u1.w, 0x7632);
    float l0 = __uint_as_float(u0.x) - __uint_as_float(u0.x & 0xFFFF0000u);
    float l1 = __uint_as_float(u0.y) - __uint_as_float(u0.y & 0xFFFF0000u);
    float l2 = __uint_as_float(u0.z) - __uint_as_float(u0.z & 0xFFFF0000u);
    float l3 = __uint_as_float(u0.w) - __uint_as_float(u0.w & 0xFFFF0000u);
    float l4 = __uint_as_float(u1.x) - __uint_as_float(u1.x & 0xFFFF0000u);
    float l5 = __uint_as_float(u1.y) - __uint_as_float(u1.y & 0xFFFF0000u);
    float l6 = __uint_as_float(u1.z) - __uint_as_float(u1.z & 0xFFFF0000u);
    float l7 = __uint_as_float(u1.w) - __uint_as_float(u1.w & 0xFFFF0000u);
    __nv_bfloat162 p0 = __float22bfloat162_rn(make_float2(l0, l1));
    __nv_bfloat162 p1 = __float22bfloat162_rn(make_float2(l2, l3));
    __nv_bfloat162 p2 = __float22bfloat162_rn(make_float2(l4, l5));
    __nv_bfloat162 p3 = __float22bfloat162_rn(make_float2(l6, l7));
    lo.x = *reinterpret_cast<uint32_t*>(&p0);
    lo.y = *reinterpret_cast<uint32_t*>(&p1);
    lo.z = *reinterpret_cast<uint32_t*>(&p2);
    lo.w = *reinterpret_cast<uint32_t*>(&p3);
}

// ============================================================================
// Kernel
// ============================================================================
__global__ void __launch_bounds__(THREADS, 1)
modlin_kernel(const float* __restrict__ x, const int* __restrict__ sel,
              const float* __restrict__ w, float* __restrict__ out)
{
    extern __shared__ char smem[];
    const int tid = threadIdx.x;
    const int wid = tid >> 5;
    const int lid = tid & 31;

    const int nt_blk = blockIdx.x;            // 0..7
    const int mt_blk = blockIdx.y;            // 0..15
    const int pi     = blockIdx.z;            // 0..15  (b,k) pair
    const int b  = pi >> 1;
    const int kk = pi & 1;
    const int m0 = mt_blk * TILE_M;
    const int n0 = nt_blk * TILE_N;

    const int e = sel[b * K_SEL + kk];

    const float* Abase = x + (((size_t)m0 * B_DIM + b) << 10);         // row stride B*IN
    const float* Bbase = w + ((((size_t)e << 10) + (size_t)n0) << 10); // row stride IN

    const uint32_t smem_base = smem_u32(smem);

    if (wid >= 8) {
        // ====================== PRODUCER (warps 8-11) =======================
        const int pid = tid - 256;             // 0..127
        for (int c = 0; c < NCHUNK; ++c) {
            const int s = c & (NSTG - 1);
            if (c >= NSTG) BAR_SYNC(5 + s);    // wait stage empty

            const int kbase = c * KC;
            char* st = smem + s * STAGE_BYTES;

            // 1024 octet-pairs per chunk: p 0..3 -> A tile, p 4..7 -> B tile
            uint4 v[16];
            #pragma unroll
            for (int p = 0; p < 8; ++p) {
                int g = pid + p * 128;
                const float* src;
                if (p < 4) {
                    int row = g >> 2, oct = g & 3;
                    src = Abase + (size_t)row * (B_DIM * IN_DIM) + kbase + oct * 8;
                } else {
                    int g2 = g - 512;
                    int row = g2 >> 2, oct = g2 & 3;
                    src = Bbase + (size_t)row * IN_DIM + kbase + oct * 8;
                }
                v[2 * p]     = *reinterpret_cast<const uint4*>(src);
                v[2 * p + 1] = *reinterpret_cast<const uint4*>(src + 4);
            }
            #pragma unroll
            for (int p = 0; p < 8; ++p) {
                int g = pid + p * 128;
                int g2 = (p < 4) ? g : g - 512;
                int row = g2 >> 2, oct = g2 & 3;
                uint4 hi, lo;
                split_oct(v[2 * p], v[2 * p + 1], hi, lo);
                uint32_t sw = sw64((uint32_t)(row * 64 + oct * 16));
                char* hiT = st + ((p < 4) ? 0 : 2 * BF_TILE);
                *reinterpret_cast<uint4*>(hiT + sw) = hi;
                *reinterpret_cast<uint4*>(hiT + BF_TILE + sw) = lo;
            }
            BAR_ARRIVE(1 + s);                 // stage full
        }
        return;
    }

    // ======================== CONSUMER (warps 0-7) ==========================
    const int warp_m = (wid & 3) * 32;         // 4 warps in m
    const int warp_n = (wid >> 2) * 64;        // 2 warps in n
    const int tile = lid >> 3;                 // ldmatrix sub-tile 0..3
    const int trow = lid & 7;
    const int qr = lid >> 2;                   // mma fragment row
    const int qc = lid & 3;

    // ldmatrix relative offsets (swizzle-invariant to tile bases)
    uint32_t aOff[2][2], bOff[4][2];
    #pragma unroll
    for (int mt = 0; mt < 2; ++mt)
        #pragma unroll
        for (int k16 = 0; k16 < 2; ++k16) {
            int row = warp_m + mt * 16 + ((tile & 1) << 3) + trow;
            int kb  = k16 * 32 + ((tile >> 1) << 4);
            aOff[mt][k16] = sw64((uint32_t)(row * 64 + kb));
        }
    #pragma unroll
    for (int nt2 = 0; nt2 < 4; ++nt2)
        #pragma unroll
        for (int k16 = 0; k16 < 2; ++k16) {
            int row = warp_n + nt2 * 16 + ((tile >> 1) << 3) + trow;
            int kb  = k16 * 32 + ((tile & 1) << 4);
            bOff[nt2][k16] = sw64((uint32_t)(row * 64 + kb));
        }

    float acc[2][8][4];
    #pragma unroll
    for (int i = 0; i < 2; ++i)
        #pragma unroll
        for (int j = 0; j < 8; ++j)
            #pragma unroll
            for (int v = 0; v < 4; ++v) acc[i][j][v] = 0.0f;

    for (int c = 0; c < NCHUNK; ++c) {
        const int s = c & (NSTG - 1);
        BAR_SYNC(1 + s);                       // wait stage full

        const uint32_t bfB = smem_base + s * STAGE_BYTES;
        const uint32_t ahB = bfB;
        const uint32_t alB = bfB + BF_TILE;
        const uint32_t bhB = bfB + 2 * BF_TILE;
        const uint32_t blB = bfB + 3 * BF_TILE;

        #pragma unroll
        for (int k16 = 0; k16 < 2; ++k16) {
            uint32_t ah[2][4], al[2][4], bh[8][2], bl[8][2];
            #pragma unroll
            for (int mt = 0; mt < 2; ++mt) {
                ldsm4(ah[mt], ahB + aOff[mt][k16]);
                ldsm4(al[mt], alB + aOff[mt][k16]);
            }
            #pragma unroll
            for (int nt2 = 0; nt2 < 4; ++nt2) {
                uint32_t r[4];
                ldsm4(r, bhB + bOff[nt2][k16]);
                bh[2 * nt2][0] = r[0]; bh[2 * nt2][1] = r[1];
                bh[2 * nt2 + 1][0] = r[2]; bh[2 * nt2 + 1][1] = r[3];
                ldsm4(r, blB + bOff[nt2][k16]);
                bl[2 * nt2][0] = r[0]; bl[2 * nt2][1] = r[1];
                bl[2 * nt2 + 1][0] = r[2]; bl[2 * nt2 + 1][1] = r[3];
            }
            // 3-term split: hh + hl + lh (16 independent accs between reuses)
            #pragma unroll
            for (int mt = 0; mt < 2; ++mt)
                #pragma unroll
                for (int nt = 0; nt < 8; ++nt)
                    mma16816(acc[mt][nt], ah[mt], bh[nt]);
            #pragma unroll
            for (int mt = 0; mt < 2; ++mt)
                #pragma unroll
                for (int nt = 0; nt < 8; ++nt)
                    mma16816(acc[mt][nt], ah[mt], bl[nt]);
            #pragma unroll
            for (int mt = 0; mt < 2; ++mt)
                #pragma unroll
                for (int nt = 0; nt < 8; ++nt)
                    mma16816(acc[mt][nt], al[mt], bh[nt]);
        }
        BAR_ARRIVE(5 + s);                     // stage empty
    }

    // ---- epilogue: direct fp32 stores ----
    const size_t row_stride = (size_t)B_DIM * K_SEL * OUT_DIM;   // 16384 floats
    #pragma unroll
    for (int mt = 0; mt < 2; ++mt) {
        const int t = m0 + warp_m + mt * 16 + qr;
        float* orow = out + (size_t)t * row_stride
                          + ((size_t)b * K_SEL + kk) * OUT_DIM
                          + n0 + warp_n + qc * 2;
        #pragma unroll
        for (int nt = 0; nt < 8; ++nt) {
            float2 v0 = make_float2(acc[mt][nt][0], acc[mt][nt][1]);
            float2 v1 = make_float2(acc[mt][nt][2], acc[mt][nt][3]);
            *reinterpret_cast<float2*>(orow + nt * 8) = v0;
            *reinterpret_cast<float2*>(orow + nt * 8 + 8 * row_stride) = v1;
        }
    }
}

// ============================================================================
// Launch
// ============================================================================
extern "C" void kernel_launch(void* const* d_in, const int* in_sizes, int n_in,
                              void* d_out, int out_size) {
    (void)in_sizes; (void)n_in; (void)out_size;
    const float* x   = (const float*)d_in[0];
    const int*   sel = (const int*)d_in[1];
    const float* w   = (const float*)d_in[2];
    float*       out = (float*)d_out;

    cudaFuncSetAttribute(modlin_kernel,
                         cudaFuncAttributeMaxDynamicSharedMemorySize, SMEM_TOTAL);

    dim3 grid(OUT_DIM / TILE_N,            // 8
              T_DIM / TILE_M,              // 16
              B_DIM * K_SEL);              // 16
    modlin_kernel<<<grid, THREADS, SMEM_TOTAL>>>(x, sel, w, out);
}

// round 8
// speedup vs baseline: 1.5364x; 1.0084x over previous
#include <cuda_runtime.h>
#include <cuda_bf16.h>
#include <cstdint>

// ============================================================================
// ModularLinear on GB300 — base-arch build (mma.sync HMMA.16816 bf16, fp32
// acc, 3-term hi/lo split). R8: KC=64 chunks (16 barriers instead of 32),
// 3-stage ring (192 KB), interleaved LDSM/MMA phase schedule, early stage
// release (arrive after last smem read, before trailing MMAs).
//
//   out[t, b, kk*1024 + o] = sum_i x[t, b, i] * w[sel[b,kk], o, i]
//   16 independent GEMMs of 2048 x 1024 x 1024 (fp32).
// ============================================================================

#define T_DIM   2048
#define B_DIM   8
#define IN_DIM  1024
#define OUT_DIM 1024
#define K_SEL   2

#define TILE_M  128
#define TILE_N  128
#define KC      64                         // K-chunk (fp32 elements)
#define NCHUNK  (IN_DIM / KC)              // 16
#define THREADS 384                        // 256 consumer + 128 producer
#define NSTG    3

// bf16 tile: 128 rows x 64 bf16 (128B rows), SW128-swizzled -> 16KB
#define BF_TILE     (TILE_M * KC * 2)      // 16384
#define STAGE_BYTES (4 * BF_TILE)          // Ah, Al, Bh, Bl = 65536
#define SMEM_TOTAL  (NSTG * STAGE_BYTES)   // 196608

// ---------------------------------------------------------------------------
// PTX helpers (base-arch only)
// ---------------------------------------------------------------------------
__device__ __forceinline__ uint32_t smem_u32(const void* p) {
    uint32_t a;
    asm("{ .reg .u64 t; cvta.to.shared.u64 t, %1; cvt.u32.u64 %0, t; }"
        : "=r"(a) : "l"(p));
    return a;
}

#define BAR_SYNC(id)   asm volatile("bar.sync %0, %1;"   :: "r"(id), "n"(THREADS) : "memory")
#define BAR_ARRIVE(id) asm volatile("bar.arrive %0, %1;" :: "r"(id), "n"(THREADS) : "memory")

__device__ __forceinline__ void ldsm4(uint32_t* r, uint32_t addr) {
    asm volatile("ldmatrix.sync.aligned.m8n8.x4.shared.b16 {%0,%1,%2,%3}, [%4];"
                 : "=r"(r[0]), "=r"(r[1]), "=r"(r[2]), "=r"(r[3])
                 : "r"(addr));
}

// D += A * B  (m16n8k16, bf16 in, fp32 acc)
__device__ __forceinline__ void mma16816(float* c, const uint32_t* a,
                                         const uint32_t* b) {
    asm volatile(
        "mma.sync.aligned.m16n8k16.row.col.f32.bf16.bf16.f32 "
        "{%0,%1,%2,%3}, {%4,%5,%6,%7}, {%8,%9}, {%0,%1,%2,%3};"
        : "+f"(c[0]), "+f"(c[1]), "+f"(c[2]), "+f"(c[3])
        : "r"(a[0]), "r"(a[1]), "r"(a[2]), "r"(a[3]),
          "r"(b[0]), "r"(b[1]));
}

// SW128 swizzle for 128B rows (8-row x 128B atom): bits[6:4] ^= bits[9:7]
__device__ __forceinline__ uint32_t sw128(uint32_t bo) {
    return bo ^ ((bo >> 3) & 0x70);
}

// split 8 consecutive fp32 (two uint4) into hi uint4 + lo uint4 (bf16x2 x4)
__device__ __forceinline__ void split_oct(uint4 u0, uint4 u1,
                                          uint4& hi, uint4& lo) {
    hi.x = __byte_perm(u0.x, u0.y, 0x7632);
    hi.y = __byte_perm(u0.z, u0.w, 0x7632);
    hi.z = __byte_perm(u1.x, u1.y, 0x7632);
    hi.w = __byte_perm(u1.z, u1.w, 0x7632);
    float l0 = __uint_as_float(u0.x) - __uint_as_float(u0.x & 0xFFFF0000u);
    float l1 = __uint_as_float(u0.y) - __uint_as_float(u0.y & 0xFFFF0000u);
    float l2 = __uint_as_float(u0.z) - __uint_as_float(u0.z & 0xFFFF0000u);
    float l3 = __uint_as_float(u0.w) - __uint_as_float(u0.w & 0xFFFF0000u);
    float l4 = __uint_as_float(u1.x) - __uint_as_float(u1.x & 0xFFFF0000u);
    float l5 = __uint_as_float(u1.y) - __uint_as_float(u1.y & 0xFFFF0000u);
    float l6 = __uint_as_float(u1.z) - __uint_as_float(u1.z & 0xFFFF0000u);
    float l7 = __uint_as_float(u1.w) - __uint_as_float(u1.w & 0xFFFF0000u);
    __nv_bfloat162 p0 = __float22bfloat162_rn(make_float2(l0, l1));
    __nv_bfloat162 p1 = __float22bfloat162_rn(make_float2(l2, l3));
    __nv_bfloat162 p2 = __float22bfloat162_rn(make_float2(l4, l5));
    __nv_bfloat162 p3 = __float22bfloat162_rn(make_float2(l6, l7));
    lo.x = *reinterpret_cast<uint32_t*>(&p0);
    lo.y = *reinterpret_cast<uint32_t*>(&p1);
    lo.z = *reinterpret_cast<uint32_t*>(&p2);
    lo.w = *reinterpret_cast<uint32_t*>(&p3);
}

// ============================================================================
// Kernel
// ============================================================================
__global__ void __launch_bounds__(THREADS, 1)
modlin_kernel(const float* __restrict__ x, const int* __restrict__ sel,
              const float* __restrict__ w, float* __restrict__ out)
{
    extern __shared__ char smem[];
    const int tid = threadIdx.x;
    const int wid = tid >> 5;
    const int lid = tid & 31;

    const int nt_blk = blockIdx.x;            // 0..7
    const int mt_blk = blockIdx.y;            // 0..15
    const int pi     = blockIdx.z;            // 0..15  (b,k) pair
    const int b  = pi >> 1;
    const int kk = pi & 1;
    const int m0 = mt_blk * TILE_M;
    const int n0 = nt_blk * TILE_N;

    const int e = sel[b * K_SEL + kk];

    const float* Abase = x + (((size_t)m0 * B_DIM + b) << 10);         // row stride B*IN
    const float* Bbase = w + ((((size_t)e << 10) + (size_t)n0) << 10); // row stride IN

    const uint32_t smem_base = smem_u32(smem);

    if (wid >= 8) {
        // ====================== PRODUCER (warps 8-11) =======================
        const int pid = tid - 256;             // 0..127
        int s = 0;
        for (int c = 0; c < NCHUNK; ++c) {
            if (c >= NSTG) BAR_SYNC(5 + s);    // wait stage empty

            const int kbase = c * KC;
            char* st = smem + s * STAGE_BYTES;

            // A tile: 128 rows x 64 elems = 1024 octs (8 elems = 32B each)
            #pragma unroll
            for (int half = 0; half < 2; ++half) {    // 0 = A, 1 = B
                char* hiT = st + half * 2 * BF_TILE;
                uint4 v[16];
                #pragma unroll
                for (int p = 0; p < 8; ++p) {
                    int g = pid + p * 128;            // oct index 0..1023
                    int row = g >> 3, oct = g & 7;
                    const float* src = half == 0
                        ? Abase + (size_t)row * (B_DIM * IN_DIM) + kbase + oct * 8
                        : Bbase + (size_t)row * IN_DIM + kbase + oct * 8;
                    v[2 * p]     = *reinterpret_cast<const uint4*>(src);
                    v[2 * p + 1] = *reinterpret_cast<const uint4*>(src + 4);
                }
                #pragma unroll
                for (int p = 0; p < 8; ++p) {
                    int g = pid + p * 128;
                    int row = g >> 3, oct = g & 7;
                    uint4 hi, lo;
                    split_oct(v[2 * p], v[2 * p + 1], hi, lo);
                    uint32_t sw = sw128((uint32_t)(row * 128 + oct * 16));
                    *reinterpret_cast<uint4*>(hiT + sw) = hi;
                    *reinterpret_cast<uint4*>(hiT + BF_TILE + sw) = lo;
                }
            }
            BAR_ARRIVE(1 + s);                 // stage full
            if (++s == NSTG) s = 0;
        }
        return;
    }

    // ======================== CONSUMER (warps 0-7) ==========================
    const int warp_m = (wid & 3) * 32;         // 4 warps in m
    const int warp_n = (wid >> 2) * 64;        // 2 warps in n
    const int tile = lid >> 3;                 // ldmatrix sub-tile 0..3
    const int trow = lid & 7;
    const int qr = lid >> 2;                   // mma fragment row
    const int qc = lid & 3;

    // ldmatrix relative offsets per k16 phase (128B rows, SW128)
    uint32_t aOff[2][4], bOff[4][4];
    #pragma unroll
    for (int mt = 0; mt < 2; ++mt)
        #pragma unroll
        for (int k16 = 0; k16 < 4; ++k16) {
            int row = warp_m + mt * 16 + ((tile & 1) << 3) + trow;
            int kb  = k16 * 32 + ((tile >> 1) << 4);
            aOff[mt][k16] = sw128((uint32_t)(row * 128 + kb));
        }
    #pragma unroll
    for (int nt2 = 0; nt2 < 4; ++nt2)
        #pragma unroll
        for (int k16 = 0; k16 < 4; ++k16) {
            int row = warp_n + nt2 * 16 + ((tile >> 1) << 3) + trow;
            int kb  = k16 * 32 + ((tile & 1) << 4);
            bOff[nt2][k16] = sw128((uint32_t)(row * 128 + kb));
        }

    float acc[2][8][4];
    #pragma unroll
    for (int i = 0; i < 2; ++i)
        #pragma unroll
        for (int j = 0; j < 8; ++j)
            #pragma unroll
            for (int v = 0; v < 4; ++v) acc[i][j][v] = 0.0f;

    int s = 0;
    for (int c = 0; c < NCHUNK; ++c) {
        BAR_SYNC(1 + s);                       // wait stage full

        const uint32_t bfB = smem_base + s * STAGE_BYTES;
        const uint32_t ahB = bfB;
        const uint32_t alB = bfB + BF_TILE;
        const uint32_t bhB = bfB + 2 * BF_TILE;
        const uint32_t blB = bfB + 3 * BF_TILE;

        #pragma unroll
        for (int k16 = 0; k16 < 4; ++k16) {
            uint32_t ah[2][4], al[2][4], bh[8][2], bl[8][2];

            // -- hi fragments first, then hh MMAs --
            #pragma unroll
            for (int mt = 0; mt < 2; ++mt)
                ldsm4(ah[mt], ahB + aOff[mt][k16]);
            #pragma unroll
            for (int nt2 = 0; nt2 < 4; ++nt2) {
                uint32_t r[4];
                ldsm4(r, bhB + bOff[nt2][k16]);
                bh[2 * nt2][0] = r[0]; bh[2 * nt2][1] = r[1];
                bh[2 * nt2 + 1][0] = r[2]; bh[2 * nt2 + 1][1] = r[3];
            }
            #pragma unroll
            for (int mt = 0; mt < 2; ++mt)
                #pragma unroll
                for (int nt = 0; nt < 8; ++nt)
                    mma16816(acc[mt][nt], ah[mt], bh[nt]);

            // -- lo fragments (sandwiched between MMA bursts) --
            #pragma unroll
            for (int mt = 0; mt < 2; ++mt)
                ldsm4(al[mt], alB + aOff[mt][k16]);
            #pragma unroll
            for (int nt2 = 0; nt2 < 4; ++nt2) {
                uint32_t r[4];
                ldsm4(r, blB + bOff[nt2][k16]);
                bl[2 * nt2][0] = r[0]; bl[2 * nt2][1] = r[1];
                bl[2 * nt2 + 1][0] = r[2]; bl[2 * nt2 + 1][1] = r[3];
            }

            // early release: last smem read of this stage just issued
            if (k16 == 3) BAR_ARRIVE(5 + s);

            #pragma unroll
            for (int mt = 0; mt < 2; ++mt)
                #pragma unroll
                for (int nt = 0; nt < 8; ++nt)
                    mma16816(acc[mt][nt], ah[mt], bl[nt]);
            #pragma unroll
            for (int mt = 0; mt < 2; ++mt)
                #pragma unroll
                for (int nt = 0; nt < 8; ++nt)
                    mma16816(acc[mt][nt], al[mt], bh[nt]);
        }
        if (++s == NSTG) s = 0;
    }

    // ---- epilogue: direct fp32 stores ----
    const size_t row_stride = (size_t)B_DIM * K_SEL * OUT_DIM;   // 16384 floats
    #pragma unroll
    for (int mt = 0; mt < 2; ++mt) {
        const int t = m0 + warp_m + mt * 16 + qr;
        float* orow = out + (size_t)t * row_stride
                          + ((size_t)b * K_SEL + kk) * OUT_DIM
                          + n0 + warp_n + qc * 2;
        #pragma unroll
        for (int nt = 0; nt < 8; ++nt) {
            float2 v0 = make_float2(acc[mt][nt][0], acc[mt][nt][1]);
            float2 v1 = make_float2(acc[mt][nt][2], acc[mt][nt][3]);
            *reinterpret_cast<float2*>(orow + nt * 8) = v0;
            *reinterpret_cast<float2*>(orow + nt * 8 + 8 * row_stride) = v1;
        }
    }
}

// ============================================================================
// Launch
// ============================================================================
extern "C" void kernel_launch(void* const* d_in, const int* in_sizes, int n_in,
                              void* d_out, int out_size) {
    (void)in_sizes; (void)n_in; (void)out_size;
    const float* x   = (const float*)d_in[0];
    const int*   sel = (const int*)d_in[1];
    const float* w   = (const float*)d_in[2];
    float*       out = (float*)d_out;

    cudaFuncSetAttribute(modlin_kernel,
                         cudaFuncAttributeMaxDynamicSharedMemorySize, SMEM_TOTAL);

    dim3 grid(OUT_DIM / TILE_N,            // 8
              T_DIM / TILE_M,              // 16
              B_DIM * K_SEL);              // 16
    modlin_kernel<<<grid, THREADS, SMEM_TOTAL>>>(x, sel, w, out);
}